// round 16
// baseline (speedup 1.0000x reference)
#include <cuda_runtime.h>
#include <cuda_fp16.h>

#define HWSZ 36864   // 192*192
#define WIMG 192

__global__ void zero_out_kernel(float* __restrict__ out, int n4) {
    int i = blockIdx.x * blockDim.x + threadIdx.x;
    if (i < n4) reinterpret_cast<float4*>(out)[i] = make_float4(0.f, 0.f, 0.f, 0.f);
}

__device__ __forceinline__ float ex2f(float a) {
    float r;
    asm("ex2.approx.ftz.f32 %0, %1;" : "=f"(r) : "f"(a));
    return r;
}

__device__ __forceinline__ void split2(float a, float b, unsigned& hi, unsigned& lo) {
    __half2 h = __floats2half2_rn(a, b);
    float ra = a - __low2float(h);
    float rb = b - __high2float(h);
    __half2 l = __floats2half2_rn(ra, rb);
    hi = *reinterpret_cast<unsigned*>(&h);
    lo = *reinterpret_cast<unsigned*>(&l);
}

__device__ __forceinline__ unsigned pack_h2(float a, float b) {
    __half2 h = __floats2half2_rn(a, b);
    return *reinterpret_cast<unsigned*>(&h);
}

__device__ __forceinline__ void mma16808(float c[4], unsigned a0, unsigned a1, unsigned b0) {
    asm volatile(
        "mma.sync.aligned.m16n8k8.row.col.f32.f16.f16.f32 "
        "{%0,%1,%2,%3}, {%4,%5}, {%6}, {%0,%1,%2,%3};"
        : "+f"(c[0]), "+f"(c[1]), "+f"(c[2]), "+f"(c[3])
        : "r"(a0), "r"(a1), "r"(b0));
}

__device__ __forceinline__ void red2(float* p, float a, float b) {
    asm volatile("red.global.add.v2.f32 [%0], {%1, %2};"
                 :: "l"(p), "f"(a), "f"(b) : "memory");
}

// shared memory word offsets
#define OFF_QHI 0            // 64*12 = 768
#define OFF_QLO 768          // 768
#define OFF_KHI 1536         // 768
#define OFF_VH  2304         // 24*36 = 864
#define OFF_CS  3168         // 64
#define OFF_SN  3232         // 64
#define OFF_SCL 3296         // 64
#define SMEM_WORDS 3360      // 13.4 KB
// O overlay: [24 ch][pitch 66] floats (1584 words) over Q tiles + freed K head
#define OPITCH 66

// One 128-thread CTA per (window, head): 4 warps, one 16-row block each.
// 2-term Q x 1-term K (fp16 split-compensated QK), 1-term V.
__global__ __launch_bounds__(128, 7) void wdwa_attn_kernel(
    const float* __restrict__ x,    // (576, 192, 192)
    const float* __restrict__ fc,   // (8, 8, 2) cos/sin
    const float* __restrict__ wgt,  // (192, 192)
    float* __restrict__ out)        // (192, 192, 192)
{
    __shared__ unsigned SM[SMEM_WORDS];
    unsigned* Qhi = SM + OFF_QHI;
    unsigned* Qlo = SM + OFF_QLO;
    unsigned* Khi = SM + OFF_KHI;
    unsigned* Vh  = SM + OFF_VH;
    float* cs  = reinterpret_cast<float*>(SM + OFF_CS);
    float* sn  = reinterpret_cast<float*>(SM + OFF_SN);
    float* scl = reinterpret_cast<float*>(SM + OFF_SCL);
    float* Osm = reinterpret_cast<float*>(SM);   // overlay (post-mainloop)

    const int wi   = blockIdx.x;     // 0..1023 = ih*64 + iw*4 + g
    const int head = blockIdx.y;     // 0..7
    const int tid  = threadIdx.x;    // 0..127
    const int warp = tid >> 5;
    const int lane = tid & 31;

    const int ih = wi >> 6;
    const int rem = wi & 63;
    const int iw = rem >> 2;
    const int g  = rem & 3;
    const int rshift = (g & 1) ? 6 : 0;
    const int cshift = (g & 2) ? 6 : 0;

    if (tid < 64) { cs[tid] = fc[2 * tid]; sn[tid] = fc[2 * tid + 1]; }

    const int qb = head * 24;
    const int kb = 192 + head * 24;
    const int vb = 384 + head * 24;

    auto srcOff = [&](int p) -> int {
        const int y = p >> 3, xx = p & 7;
        int sr = ih * 12 + y;
        if (rshift) sr = (sr < 186) ? sr + 6 : 376 - sr;
        int sc = iw * 12 + xx;
        if (cshift) sc = (sc < 186) ? sc + 6 : 376 - sc;
        return sr * WIMG + sc;
    };

    // ---- global loads ----
    const int vpix = tid & 63;
    const int vch0 = (tid >> 6) * 12;
    const float* vp = x + srcOff(vpix) + (vb + vch0) * HWSZ;
    float v[12];
#pragma unroll
    for (int c = 0; c < 12; c++) v[c] = vp[c * HWSZ];

    const int row = tid & 63;
    const bool isQ = (tid < 64);
    const float* rp = x + srcOff(row) + (isQ ? qb : kb) * HWSZ;
    float rqk[24];
#pragma unroll
    for (int c = 0; c < 24; c++) rqk[c] = rp[c * HWSZ];

    __syncthreads();  // cs/sn ready

    // hs_pe rotation
    {
        const int ry = row >> 3, rx = row & 7;
#pragma unroll
        for (int t = 0; t < 8; t++) {
            const float cy = cs[ry * 8 + t], sy = sn[ry * 8 + t];
            const float cx = cs[rx * 8 + t], sx = sn[rx * 8 + t];
            float a = rqk[3*t], b = rqk[3*t+1], c2 = rqk[3*t+2];
            float a2 = a * cy - b * sy;
            float b2 = a * sy + b * cy;
            rqk[3*t]   = a2;
            rqk[3*t+1] = b2 * cx - c2 * sx;
            rqk[3*t+2] = b2 * sx + c2 * cx;
        }
    }

    const float QSCALE = 0.2944887f;   // 1/sqrt(24) * log2(e)
    if (isQ) {
#pragma unroll
        for (int j = 0; j < 12; j++) {
            unsigned hi, lo;
            split2(rqk[2*j] * QSCALE, rqk[2*j+1] * QSCALE, hi, lo);
            Qhi[row * 12 + j] = hi;
            Qlo[row * 12 + j] = lo;
        }
    } else {
#pragma unroll
        for (int j = 0; j < 12; j++)
            Khi[row * 12 + j] = pack_h2(rqk[2*j], rqk[2*j+1]);
    }

#pragma unroll
    for (int c = 0; c < 12; c++) {
        const float other = __shfl_xor_sync(0xffffffff, v[c], 1);
        if (!(vpix & 1)) Vh[(vch0 + c) * 36 + (vpix >> 1)] = pack_h2(v[c], other);
    }
    __syncthreads();

    // ---------------- mainloop: warp owns row-block warp ----------------
    const int qr = lane >> 2;
    const int qc = lane & 3;
    const int ar0 = warp * 16 + qr;

    unsigned aQh[3][2], aQl[3][2];
#pragma unroll
    for (int c = 0; c < 3; c++) {
        const int h2c = 4 * c + qc;
        aQh[c][0] = Qhi[ar0 * 12 + h2c];
        aQh[c][1] = Qhi[(ar0 + 8) * 12 + h2c];
        aQl[c][0] = Qlo[ar0 * 12 + h2c];
        aQl[c][1] = Qlo[(ar0 + 8) * 12 + h2c];
    }

    float s8[8][4];
#pragma unroll
    for (int nt = 0; nt < 8; nt++) { s8[nt][0]=0.f; s8[nt][1]=0.f; s8[nt][2]=0.f; s8[nt][3]=0.f; }
#pragma unroll
    for (int c = 0; c < 3; c++) {
#pragma unroll
        for (int nt = 0; nt < 8; nt++) {
            const unsigned bh = Khi[(nt * 8 + qr) * 12 + 4 * c + qc];
            mma16808(s8[nt], aQh[c][0], aQh[c][1], bh);
            mma16808(s8[nt], aQl[c][0], aQl[c][1], bh);
        }
    }

    float m0 = -1e30f, m1 = -1e30f;
#pragma unroll
    for (int nt = 0; nt < 8; nt++) {
        m0 = fmaxf(m0, fmaxf(s8[nt][0], s8[nt][1]));
        m1 = fmaxf(m1, fmaxf(s8[nt][2], s8[nt][3]));
    }
    m0 = fmaxf(m0, __shfl_xor_sync(0xffffffff, m0, 1));
    m0 = fmaxf(m0, __shfl_xor_sync(0xffffffff, m0, 2));
    m1 = fmaxf(m1, __shfl_xor_sync(0xffffffff, m1, 1));
    m1 = fmaxf(m1, __shfl_xor_sync(0xffffffff, m1, 2));

    float den0 = 0.f, den1 = 0.f;
#pragma unroll
    for (int nt = 0; nt < 8; nt++) {
        s8[nt][0] = ex2f(s8[nt][0] - m0);
        s8[nt][1] = ex2f(s8[nt][1] - m0);
        s8[nt][2] = ex2f(s8[nt][2] - m1);
        s8[nt][3] = ex2f(s8[nt][3] - m1);
        den0 += s8[nt][0] + s8[nt][1];
        den1 += s8[nt][2] + s8[nt][3];
    }
    den0 += __shfl_xor_sync(0xffffffff, den0, 1);
    den0 += __shfl_xor_sync(0xffffffff, den0, 2);
    den1 += __shfl_xor_sync(0xffffffff, den1, 1);
    den1 += __shfl_xor_sync(0xffffffff, den1, 2);

    float d3[3][4];
#pragma unroll
    for (int nt = 0; nt < 3; nt++) { d3[nt][0]=0.f; d3[nt][1]=0.f; d3[nt][2]=0.f; d3[nt][3]=0.f; }
#pragma unroll
    for (int kc2 = 0; kc2 < 8; kc2++) {
        unsigned p0h, p0l, p1h, p1l;
        split2(s8[kc2][0], s8[kc2][1], p0h, p0l);
        split2(s8[kc2][2], s8[kc2][3], p1h, p1l);
#pragma unroll
        for (int nt = 0; nt < 3; nt++) {
            const unsigned b = Vh[(nt * 8 + qr) * 36 + 4 * kc2 + qc];
            mma16808(d3[nt], p0h, p1h, b);
            mma16808(d3[nt], p0l, p1l, b);
        }
    }

    // ---------------- epilogue: stage O + per-pixel scale in smem ----------------
    __syncthreads();   // all reads of Q/K tiles done (O overlays them)

    if (qc == 0) {
        const float inv0 = 1.0f / den0;
        const float inv1 = 1.0f / den1;
#pragma unroll
        for (int hh = 0; hh < 2; hh++) {
            const int p  = warp * 16 + qr + 8 * hh;
            const int gr = ih * 12 + (p >> 3) + rshift;
            const int gc = iw * 12 + (p & 7) + cshift;
            const bool valid = (gr < 192) && (gc < 192);
            const float w = valid ? wgt[gr * WIMG + gc] : 1.0f;
            scl[p] = (hh ? inv1 : inv0) / w;
        }
    }

#pragma unroll
    for (int hh = 0; hh < 2; hh++) {
        const int p = warp * 16 + qr + 8 * hh;
#pragma unroll
        for (int nt = 0; nt < 3; nt++) {
            const int ch = nt * 8 + 2 * qc;
            Osm[ch * OPITCH + p]       = d3[nt][2*hh];
            Osm[(ch + 1) * OPITCH + p] = d3[nt][2*hh + 1];
        }
    }
    __syncthreads();

    // coalesced reduction: warp owns 6 channels, lane owns pixel pair (2l, 2l+1)
    {
        const int pp = lane;
        const int gr = ih * 12 + (pp >> 2) + rshift;
        const int gc = iw * 12 + ((pp & 3) << 1) + cshift;
        const bool valid = (gr < 192) && (gc < 192);
        const float s0 = scl[2 * pp];
        const float s1 = scl[2 * pp + 1];
        float* obase = out + (head * 24) * HWSZ + gr * WIMG + gc;
#pragma unroll
        for (int k = 0; k < 6; k++) {
            const int c = 6 * warp + k;
            const float2 o = *reinterpret_cast<const float2*>(Osm + c * OPITCH + 2 * pp);
            if (valid) red2(obase + c * HWSZ, o.x * s0, o.y * s1);
        }
    }
}

extern "C" void kernel_launch(void* const* d_in, const int* in_sizes, int n_in,
                              void* d_out, int out_size) {
    const float* x   = (const float*)d_in[0];
    const float* fc  = (const float*)d_in[1];
    const float* wgt = (const float*)d_in[2];
    float* out = (float*)d_out;

    const int n4 = (192 * 36864) / 4;
    zero_out_kernel<<<(n4 + 255) / 256, 256>>>(out, n4);

    dim3 grid(1024, 8);
    wdwa_attn_kernel<<<grid, 128>>>(x, fc, wgt, out);
}

// round 17
// speedup vs baseline: 1.4928x; 1.4928x over previous
#include <cuda_runtime.h>
#include <cuda_fp16.h>

#define HWSZ 36864   // 192*192
#define WIMG 192

__global__ void zero_out_kernel(float* __restrict__ out, int n4) {
    int i = blockIdx.x * blockDim.x + threadIdx.x;
    if (i < n4) reinterpret_cast<float4*>(out)[i] = make_float4(0.f, 0.f, 0.f, 0.f);
}

__device__ __forceinline__ float ex2f(float a) {
    float r;
    asm("ex2.approx.ftz.f32 %0, %1;" : "=f"(r) : "f"(a));
    return r;
}

__device__ __forceinline__ void split2(float a, float b, unsigned& hi, unsigned& lo) {
    __half2 h = __floats2half2_rn(a, b);
    float ra = a - __low2float(h);
    float rb = b - __high2float(h);
    __half2 l = __floats2half2_rn(ra, rb);
    hi = *reinterpret_cast<unsigned*>(&h);
    lo = *reinterpret_cast<unsigned*>(&l);
}

__device__ __forceinline__ unsigned pack_h2(float a, float b) {
    __half2 h = __floats2half2_rn(a, b);
    return *reinterpret_cast<unsigned*>(&h);
}

__device__ __forceinline__ void mma16808(float c[4], unsigned a0, unsigned a1, unsigned b0) {
    asm volatile(
        "mma.sync.aligned.m16n8k8.row.col.f32.f16.f16.f32 "
        "{%0,%1,%2,%3}, {%4,%5}, {%6}, {%0,%1,%2,%3};"
        : "+f"(c[0]), "+f"(c[1]), "+f"(c[2]), "+f"(c[3])
        : "r"(a0), "r"(a1), "r"(b0));
}

__device__ __forceinline__ void red2(float* p, float a, float b) {
    asm volatile("red.global.add.v2.f32 [%0], {%1, %2};"
                 :: "l"(p), "f"(a), "f"(b) : "memory");
}

// shared memory word offsets
#define OFF_QHI 0            // 64*12 = 768
#define OFF_QLO 768          // 768
#define OFF_KHI 1536         // 768
#define OFF_VH  2304         // 24*36 = 864
#define OFF_CS  3168         // 64
#define OFF_SN  3232         // 64
#define OFF_SCL 3296         // 64
#define SMEM_WORDS 3360      // 13.4 KB
// O overlay: [24 ch][pitch 66] floats (1584 words) over Q tiles + freed K head
#define OPITCH 66

// One 128-thread CTA per (window, head): 4 warps, one 16-row block each.
// 2-term Q x 1-term K (fp16 split-compensated QK), 1-term V.
// maxBlocks=6: reg budget ~78 avoids the spill regression seen at 7.
__global__ __launch_bounds__(128, 6) void wdwa_attn_kernel(
    const float* __restrict__ x,    // (576, 192, 192)
    const float* __restrict__ fc,   // (8, 8, 2) cos/sin
    const float* __restrict__ wgt,  // (192, 192)
    float* __restrict__ out)        // (192, 192, 192)
{
    __shared__ unsigned SM[SMEM_WORDS];
    unsigned* Qhi = SM + OFF_QHI;
    unsigned* Qlo = SM + OFF_QLO;
    unsigned* Khi = SM + OFF_KHI;
    unsigned* Vh  = SM + OFF_VH;
    float* cs  = reinterpret_cast<float*>(SM + OFF_CS);
    float* sn  = reinterpret_cast<float*>(SM + OFF_SN);
    float* scl = reinterpret_cast<float*>(SM + OFF_SCL);
    float* Osm = reinterpret_cast<float*>(SM);   // overlay (post-mainloop)

    const int wi   = blockIdx.x;     // 0..1023 = ih*64 + iw*4 + g
    const int head = blockIdx.y;     // 0..7
    const int tid  = threadIdx.x;    // 0..127
    const int warp = tid >> 5;
    const int lane = tid & 31;

    const int ih = wi >> 6;
    const int rem = wi & 63;
    const int iw = rem >> 2;
    const int g  = rem & 3;
    const int rshift = (g & 1) ? 6 : 0;
    const int cshift = (g & 2) ? 6 : 0;

    if (tid < 64) { cs[tid] = fc[2 * tid]; sn[tid] = fc[2 * tid + 1]; }

    const int qb = head * 24;
    const int kb = 192 + head * 24;
    const int vb = 384 + head * 24;

    auto srcOff = [&](int p) -> int {
        const int y = p >> 3, xx = p & 7;
        int sr = ih * 12 + y;
        if (rshift) sr = (sr < 186) ? sr + 6 : 376 - sr;
        int sc = iw * 12 + xx;
        if (cshift) sc = (sc < 186) ? sc + 6 : 376 - sc;
        return sr * WIMG + sc;
    };

    // ---- global loads ----
    const int vpix = tid & 63;
    const int vch0 = (tid >> 6) * 12;
    const float* vp = x + srcOff(vpix) + (vb + vch0) * HWSZ;
    float v[12];
#pragma unroll
    for (int c = 0; c < 12; c++) v[c] = vp[c * HWSZ];

    const int row = tid & 63;
    const bool isQ = (tid < 64);
    const float* rp = x + srcOff(row) + (isQ ? qb : kb) * HWSZ;
    float rqk[24];
#pragma unroll
    for (int c = 0; c < 24; c++) rqk[c] = rp[c * HWSZ];

    __syncthreads();  // cs/sn ready

    // hs_pe rotation
    {
        const int ry = row >> 3, rx = row & 7;
#pragma unroll
        for (int t = 0; t < 8; t++) {
            const float cy = cs[ry * 8 + t], sy = sn[ry * 8 + t];
            const float cx = cs[rx * 8 + t], sx = sn[rx * 8 + t];
            float a = rqk[3*t], b = rqk[3*t+1], c2 = rqk[3*t+2];
            float a2 = a * cy - b * sy;
            float b2 = a * sy + b * cy;
            rqk[3*t]   = a2;
            rqk[3*t+1] = b2 * cx - c2 * sx;
            rqk[3*t+2] = b2 * sx + c2 * cx;
        }
    }

    const float QSCALE = 0.2944887f;   // 1/sqrt(24) * log2(e)
    if (isQ) {
#pragma unroll
        for (int j = 0; j < 12; j++) {
            unsigned hi, lo;
            split2(rqk[2*j] * QSCALE, rqk[2*j+1] * QSCALE, hi, lo);
            Qhi[row * 12 + j] = hi;
            Qlo[row * 12 + j] = lo;
        }
    } else {
#pragma unroll
        for (int j = 0; j < 12; j++)
            Khi[row * 12 + j] = pack_h2(rqk[2*j], rqk[2*j+1]);
    }

#pragma unroll
    for (int c = 0; c < 12; c++) {
        const float other = __shfl_xor_sync(0xffffffff, v[c], 1);
        if (!(vpix & 1)) Vh[(vch0 + c) * 36 + (vpix >> 1)] = pack_h2(v[c], other);
    }
    __syncthreads();

    // ---------------- mainloop: warp owns row-block warp ----------------
    const int qr = lane >> 2;
    const int qc = lane & 3;
    const int ar0 = warp * 16 + qr;

    unsigned aQh[3][2], aQl[3][2];
#pragma unroll
    for (int c = 0; c < 3; c++) {
        const int h2c = 4 * c + qc;
        aQh[c][0] = Qhi[ar0 * 12 + h2c];
        aQh[c][1] = Qhi[(ar0 + 8) * 12 + h2c];
        aQl[c][0] = Qlo[ar0 * 12 + h2c];
        aQl[c][1] = Qlo[(ar0 + 8) * 12 + h2c];
    }

    float s8[8][4];
#pragma unroll
    for (int nt = 0; nt < 8; nt++) { s8[nt][0]=0.f; s8[nt][1]=0.f; s8[nt][2]=0.f; s8[nt][3]=0.f; }
#pragma unroll
    for (int c = 0; c < 3; c++) {
#pragma unroll
        for (int nt = 0; nt < 8; nt++) {
            const unsigned bh = Khi[(nt * 8 + qr) * 12 + 4 * c + qc];
            mma16808(s8[nt], aQh[c][0], aQh[c][1], bh);
            mma16808(s8[nt], aQl[c][0], aQl[c][1], bh);
        }
    }

    float m0 = -1e30f, m1 = -1e30f;
#pragma unroll
    for (int nt = 0; nt < 8; nt++) {
        m0 = fmaxf(m0, fmaxf(s8[nt][0], s8[nt][1]));
        m1 = fmaxf(m1, fmaxf(s8[nt][2], s8[nt][3]));
    }
    m0 = fmaxf(m0, __shfl_xor_sync(0xffffffff, m0, 1));
    m0 = fmaxf(m0, __shfl_xor_sync(0xffffffff, m0, 2));
    m1 = fmaxf(m1, __shfl_xor_sync(0xffffffff, m1, 1));
    m1 = fmaxf(m1, __shfl_xor_sync(0xffffffff, m1, 2));

    float den0 = 0.f, den1 = 0.f;
#pragma unroll
    for (int nt = 0; nt < 8; nt++) {
        s8[nt][0] = ex2f(s8[nt][0] - m0);
        s8[nt][1] = ex2f(s8[nt][1] - m0);
        s8[nt][2] = ex2f(s8[nt][2] - m1);
        s8[nt][3] = ex2f(s8[nt][3] - m1);
        den0 += s8[nt][0] + s8[nt][1];
        den1 += s8[nt][2] + s8[nt][3];
    }
    den0 += __shfl_xor_sync(0xffffffff, den0, 1);
    den0 += __shfl_xor_sync(0xffffffff, den0, 2);
    den1 += __shfl_xor_sync(0xffffffff, den1, 1);
    den1 += __shfl_xor_sync(0xffffffff, den1, 2);

    float d3[3][4];
#pragma unroll
    for (int nt = 0; nt < 3; nt++) { d3[nt][0]=0.f; d3[nt][1]=0.f; d3[nt][2]=0.f; d3[nt][3]=0.f; }
#pragma unroll
    for (int kc2 = 0; kc2 < 8; kc2++) {
        unsigned p0h, p0l, p1h, p1l;
        split2(s8[kc2][0], s8[kc2][1], p0h, p0l);
        split2(s8[kc2][2], s8[kc2][3], p1h, p1l);
#pragma unroll
        for (int nt = 0; nt < 3; nt++) {
            const unsigned b = Vh[(nt * 8 + qr) * 36 + 4 * kc2 + qc];
            mma16808(d3[nt], p0h, p1h, b);
            mma16808(d3[nt], p0l, p1l, b);
        }
    }

    // ---------------- epilogue: stage O + per-pixel scale in smem ----------------
    __syncthreads();   // all reads of Q/K tiles done (O overlays them)

    if (qc == 0) {
        const float inv0 = 1.0f / den0;
        const float inv1 = 1.0f / den1;
#pragma unroll
        for (int hh = 0; hh < 2; hh++) {
            const int p  = warp * 16 + qr + 8 * hh;
            const int gr = ih * 12 + (p >> 3) + rshift;
            const int gc = iw * 12 + (p & 7) + cshift;
            const bool valid = (gr < 192) && (gc < 192);
            const float w = valid ? wgt[gr * WIMG + gc] : 1.0f;
            scl[p] = (hh ? inv1 : inv0) / w;
        }
    }

#pragma unroll
    for (int hh = 0; hh < 2; hh++) {
        const int p = warp * 16 + qr + 8 * hh;
#pragma unroll
        for (int nt = 0; nt < 3; nt++) {
            const int ch = nt * 8 + 2 * qc;
            Osm[ch * OPITCH + p]       = d3[nt][2*hh];
            Osm[(ch + 1) * OPITCH + p] = d3[nt][2*hh + 1];
        }
    }
    __syncthreads();

    // coalesced reduction: warp owns 6 channels, lane owns pixel pair (2l, 2l+1)
    {
        const int pp = lane;
        const int gr = ih * 12 + (pp >> 2) + rshift;
        const int gc = iw * 12 + ((pp & 3) << 1) + cshift;
        const bool valid = (gr < 192) && (gc < 192);
        const float s0 = scl[2 * pp];
        const float s1 = scl[2 * pp + 1];
        float* obase = out + (head * 24) * HWSZ + gr * WIMG + gc;
#pragma unroll
        for (int k = 0; k < 6; k++) {
            const int c = 6 * warp + k;
            const float2 o = *reinterpret_cast<const float2*>(Osm + c * OPITCH + 2 * pp);
            if (valid) red2(obase + c * HWSZ, o.x * s0, o.y * s1);
        }
    }
}

extern "C" void kernel_launch(void* const* d_in, const int* in_sizes, int n_in,
                              void* d_out, int out_size) {
    const float* x   = (const float*)d_in[0];
    const float* fc  = (const float*)d_in[1];
    const float* wgt = (const float*)d_in[2];
    float* out = (float*)d_out;

    const int n4 = (192 * 36864) / 4;
    zero_out_kernel<<<(n4 + 255) / 256, 256>>>(out, n4);

    dim3 grid(1024, 8);
    wdwa_attn_kernel<<<grid, 128>>>(x, fc, wgt, out);
}